// round 4
// baseline (speedup 1.0000x reference)
#include <cuda_runtime.h>
#include <cuda_bf16.h>
#include <cstdint>

#define T_LEN 16384
#define HID   128
#define G4    512   // 4*HID gate rows

// ---------------- scratch (static device globals; no allocation) -------------
// gx layout: [t][unit 0..127][gate i,f,g,o]  (float4 per unit)
__device__ float g_gx[4u * T_LEN * G4];   // [l0f,l0b,l1f,l1b]
__device__ float g_h0[T_LEN * 2 * HID];   // layer0 output [t][256]
__device__ float g_h1[T_LEN * 2 * HID];   // layer1 output [t][256]

// ---------------- helpers ----------------------------------------------------
__device__ __forceinline__ void fma2(unsigned long long& d,
                                     unsigned long long a,
                                     unsigned long long b) {
    asm("fma.rn.f32x2 %0, %1, %2, %0;" : "+l"(d) : "l"(a), "l"(b));
}
__device__ __forceinline__ float unpack_sum(unsigned long long v) {
    float lo, hi;
    asm("mov.b64 {%0,%1}, %2;" : "=f"(lo), "=f"(hi) : "l"(v));
    return lo + hi;
}
__device__ __forceinline__ uint32_t smem_u32(const void* p) {
    uint32_t a;
    asm("{ .reg .u64 t; cvta.to.shared.u64 t, %1; cvt.u32.u64 %0, t; }"
        : "=r"(a) : "l"(p));
    return a;
}

// ---------------- kernel 1: layer-0 input projection (IN=1) ------------------
__global__ void k_gx0(const float* __restrict__ x,
                      const float* __restrict__ wf, const float* __restrict__ bfi,
                      const float* __restrict__ bfh,
                      const float* __restrict__ wb, const float* __restrict__ bbi,
                      const float* __restrict__ bbh,
                      float* __restrict__ gxf, float* __restrict__ gxb) {
    unsigned idx = blockIdx.x * 256u + threadIdx.x;
    if (idx >= (unsigned)T_LEN * G4) return;
    unsigned t = idx >> 9, r = idx & 511u;             // r = gate*128 + unit
    unsigned dst = t * G4 + (r & 127u) * 4u + (r >> 7);
    float xv = x[t];
    gxf[dst] = xv * wf[r] + bfi[r] + bfh[r];
    gxb[dst] = xv * wb[r] + bbi[r] + bbh[r];
}

// ---------------- kernel 2: recurrent scan, 2-CTA cluster per direction ------
// Warp w owns units rank*64 + 4w..4w+3. Lane l: unit j=l&3, k-eighth e=l>>2.
// Weights in registers. Reduce-scatter (4 shfl) puts gate (e>>1) of unit j on
// lane l; ONE unified tanh-form activation serves all gates; 3 shfls gather
// i,f,g,o to the writer lane (e==0). Local ordering via __syncthreads only;
// remote h via DSMEM store + 64-arrive mbarrier.
__global__ void __launch_bounds__(512, 1) __cluster_dims__(2, 1, 1)
k_lstm2(const float* __restrict__ gx_f, const float* __restrict__ gx_b,
        const float* __restrict__ whh_f, const float* __restrict__ whh_b,
        float* __restrict__ hcat) {
    __shared__ alignas(16) float hbuf[2 * 136];   // [buf][half*68 + unit]
    __shared__ alignas(8) unsigned long long bar_rem;

    const int dir = blockIdx.x >> 1;
    uint32_t rank;
    asm("mov.u32 %0, %%cluster_ctarank;" : "=r"(rank));
    const float* gx  = dir ? gx_b  : gx_f;
    const float* whh = dir ? whh_b : whh_f;

    const int tid  = threadIdx.x;
    const int w    = tid >> 5;
    const int l    = tid & 31;
    const int j    = l & 3;                     // unit within warp
    const int e    = l >> 2;                    // k-eighth 0..7
    const int u    = (w << 2) | j;              // local unit 0..63
    const int gu   = (int)rank * 64 + u;        // global unit
    const int gate = e >> 1;                    // lane's activation gate
    const bool wr  = (e == 0);

    const int kA = (int)rank * 64 + e * 8;      // local-half k slice
    const int kB = (((int)rank) ^ 1) * 64 + e * 8;

    // ---- stage weights: 4 gates x 2 phases x 8 floats = 64 regs ----
    ulonglong2 wv[4][2][2];
#pragma unroll
    for (int g = 0; g < 4; g++) {
        const float* row = whh + (size_t)(g * HID + gu) * HID;
        const ulonglong2* pA = (const ulonglong2*)(row + kA);
        const ulonglong2* pB = (const ulonglong2*)(row + kB);
        wv[g][0][0] = pA[0]; wv[g][0][1] = pA[1];
        wv[g][1][0] = pB[0]; wv[g][1][1] = pB[1];
    }

    // ---- init ----
    if (tid < 272) hbuf[tid] = 0.f;
    const uint32_t br_a = smem_u32(&bar_rem);
    const uint32_t hb_a = smem_u32(hbuf);
    if (tid == 0)
        asm volatile("mbarrier.init.shared.b64 [%0], %1;"
                     :: "r"(br_a), "r"(64u) : "memory");
    __syncthreads();

    const uint32_t prank = rank ^ 1u;
    uint32_t peer_hbuf, peer_brem;
    asm("mapa.shared::cluster.u32 %0, %1, %2;"
        : "=r"(peer_hbuf) : "r"(hb_a), "r"(prank));
    asm("mapa.shared::cluster.u32 %0, %1, %2;"
        : "=r"(peer_brem) : "r"(br_a), "r"(prank));

    asm volatile("barrier.cluster.arrive.aligned;" ::: "memory");
    asm volatile("barrier.cluster.wait.aligned;" ::: "memory");

    float c = 0.f;
    const int t_first = dir ? (T_LEN - 1) : 0;
    float gx_next = gx[(size_t)t_first * G4 + gu * 4 + gate];

    for (int s = 0; s < T_LEN; ++s) {
        const int t = dir ? (T_LEN - 1 - s) : s;
        const float gxv = gx_next;
        const int rd = (s & 1) ^ 1;                   // buffer holding h(s-1)

        {   // prefetch next step's gx (off critical path)
            int t2 = dir ? (t - 1) : (t + 1);
            if (s == T_LEN - 1) t2 = t;
            gx_next = gx[(size_t)t2 * G4 + gu * 4 + gate];
        }

        unsigned long long a0 = 0ull, a1 = 0ull, a2 = 0ull, a3 = 0ull;
        // ---- phase A: local-half k ----
        {
            const ulonglong2* hA =
                (const ulonglong2*)(hbuf + rd * 136 + (int)rank * 68 + e * 8);
            ulonglong2 h0v = hA[0], h1v = hA[1];
            fma2(a0, wv[0][0][0].x, h0v.x); fma2(a0, wv[0][0][0].y, h0v.y);
            fma2(a1, wv[1][0][0].x, h0v.x); fma2(a1, wv[1][0][0].y, h0v.y);
            fma2(a2, wv[2][0][0].x, h0v.x); fma2(a2, wv[2][0][0].y, h0v.y);
            fma2(a3, wv[3][0][0].x, h0v.x); fma2(a3, wv[3][0][0].y, h0v.y);
            fma2(a0, wv[0][0][1].x, h1v.x); fma2(a0, wv[0][0][1].y, h1v.y);
            fma2(a1, wv[1][0][1].x, h1v.x); fma2(a1, wv[1][0][1].y, h1v.y);
            fma2(a2, wv[2][0][1].x, h1v.x); fma2(a2, wv[2][0][1].y, h1v.y);
            fma2(a3, wv[3][0][1].x, h1v.x); fma2(a3, wv[3][0][1].y, h1v.y);
        }
        // ---- wait for peer h(s-1) (latency overlapped by phase A) ----
        if (s) {
            const unsigned par = (unsigned)((s - 1) & 1);
            unsigned done;
            asm volatile(
                "{\n\t.reg .pred p;\n\t"
                "mbarrier.try_wait.parity.acquire.cluster.shared::cta.b64 p, [%1], %2, 0x989680;\n\t"
                "selp.b32 %0, 1, 0, p;\n\t}"
                : "=r"(done) : "r"(br_a), "r"(par) : "memory");
            while (!done) {
                asm volatile(
                    "{\n\t.reg .pred p;\n\t"
                    "mbarrier.try_wait.parity.acquire.cluster.shared::cta.b64 p, [%1], %2, 0x989680;\n\t"
                    "selp.b32 %0, 1, 0, p;\n\t}"
                    : "=r"(done) : "r"(br_a), "r"(par) : "memory");
            }
        }
        // ---- phase B: peer-half k ----
        {
            const ulonglong2* hB =
                (const ulonglong2*)(hbuf + rd * 136 + ((int)prank) * 68 + e * 8);
            ulonglong2 h0v = hB[0], h1v = hB[1];
            fma2(a0, wv[0][1][0].x, h0v.x); fma2(a0, wv[0][1][0].y, h0v.y);
            fma2(a1, wv[1][1][0].x, h0v.x); fma2(a1, wv[1][1][0].y, h0v.y);
            fma2(a2, wv[2][1][0].x, h0v.x); fma2(a2, wv[2][1][0].y, h0v.y);
            fma2(a3, wv[3][1][0].x, h0v.x); fma2(a3, wv[3][1][0].y, h0v.y);
            fma2(a0, wv[0][1][1].x, h1v.x); fma2(a0, wv[0][1][1].y, h1v.y);
            fma2(a1, wv[1][1][1].x, h1v.x); fma2(a1, wv[1][1][1].y, h1v.y);
            fma2(a2, wv[2][1][1].x, h1v.x); fma2(a2, wv[2][1][1].y, h1v.y);
            fma2(a3, wv[3][1][1].x, h1v.x); fma2(a3, wv[3][1][1].y, h1v.y);
        }

        // ---- reduce-scatter over the 8 e-lanes: 4 shfls ----
        float S0 = unpack_sum(a0);                    // i partial
        float S1 = unpack_sum(a1);                    // f
        float S2 = unpack_sum(a2);                    // g
        float S3 = unpack_sum(a3);                    // o
        float give0 = (e < 4) ? S2 : S0;
        float give1 = (e < 4) ? S3 : S1;
        float r0 = __shfl_xor_sync(0xFFFFFFFFu, give0, 16);
        float r1 = __shfl_xor_sync(0xFFFFFFFFu, give1, 16);
        float A  = ((e < 4) ? S0 : S2) + r0;          // lo: i, hi: g
        float B  = ((e < 4) ? S1 : S3) + r1;          // lo: f, hi: o
        float give2 = (e & 2) ? A : B;
        float r2 = __shfl_xor_sync(0xFFFFFFFFu, give2, 8);
        float C  = ((e & 2) ? B : A) + r2;            // e0,1:i e2,3:f e4,5:g e6,7:o
        C += __shfl_xor_sync(0xFFFFFFFFu, C, 4);

        // ---- unified activation: tanh(x)=1-2/(e^{2x}+1) ----
        float arg = C + gxv;
        float ag  = (gate == 2) ? (2.f * arg) : arg;
        float ex  = __expf(ag);
        float th  = 1.f - __fdividef(2.f, ex + 1.f);  // tanh(ag/2)
        float res = (gate == 2) ? th : (0.5f + 0.5f * th);

        // ---- gather i,f,g,o to writer lane (e==0) ----
        float fv = __shfl_sync(0xFFFFFFFFu, res, 8 + j);
        float gv = __shfl_sync(0xFFFFFFFFu, res, 16 + j);
        float ov = __shfl_sync(0xFFFFFFFFu, res, 24 + j);

        if (wr) {
            c = fv * c + res * gv;                    // res == i on e==0
            float exc = __expf(2.f * c);
            float thc = 1.f - __fdividef(2.f, exc + 1.f);
            float h = ov * thc;

            const int woff = (s & 1) * 136 + (int)rank * 68 + u;
            asm volatile("st.shared::cluster.f32 [%0], %1;"
                         :: "r"(peer_hbuf + (uint32_t)(woff * 4)), "f"(h)
                         : "memory");
            asm volatile(
                "mbarrier.arrive.release.cluster.shared::cluster.b64 _, [%0];"
                :: "r"(peer_brem) : "memory");
            hbuf[woff] = h;
            hcat[(size_t)t * (2 * HID) + dir * HID + gu] = h;
        }
        __syncthreads();                              // local h visible, WAR safe
    }

    asm volatile("barrier.cluster.arrive.aligned;" ::: "memory");
    asm volatile("barrier.cluster.wait.aligned;" ::: "memory");
}

// ---------------- kernel 3: layer-1 input projection GEMM --------------------
__global__ void __launch_bounds__(512)
k_gx1(const float* __restrict__ h0,
      const float* __restrict__ Wf, const float* __restrict__ bfi,
      const float* __restrict__ bfh,
      const float* __restrict__ Wb, const float* __restrict__ bbi,
      const float* __restrict__ bbh,
      float* __restrict__ gxf, float* __restrict__ gxb) {
    const int dir = blockIdx.y;
    const float* W  = dir ? Wb  : Wf;
    const float* bi = dir ? bbi : bfi;
    const float* bh = dir ? bbh : bfh;
    float* gx       = dir ? gxb : gxf;

    __shared__ float hs[32 * 256];
    const int t0 = blockIdx.x * 32;
    const int r  = threadIdx.x;                        // gate*128 + unit

    for (int idx = r; idx < 32 * 256; idx += 512)
        hs[idx] = h0[(size_t)t0 * 256 + idx];
    __syncthreads();

    float acc[32];
    const float bias = bi[r] + bh[r];
#pragma unroll
    for (int tt = 0; tt < 32; tt++) acc[tt] = bias;

    const float4* wrow = (const float4*)(W + (size_t)r * 256);
    for (int k4 = 0; k4 < 64; k4++) {
        float4 w4 = wrow[k4];
#pragma unroll
        for (int tt = 0; tt < 32; tt++) {
            float4 hv = *(const float4*)(hs + tt * 256 + k4 * 4);
            acc[tt] += w4.x * hv.x + w4.y * hv.y + w4.z * hv.z + w4.w * hv.w;
        }
    }
    const unsigned dst_r = (r & 127u) * 4u + (r >> 7); // [unit][gate]
#pragma unroll
    for (int tt = 0; tt < 32; tt++)
        gx[(size_t)(t0 + tt) * G4 + dst_r] = acc[tt];
}

// ---------------- kernel 4: FC head ------------------------------------------
__global__ void __launch_bounds__(128)
k_head(const float* __restrict__ h1,
       const float* __restrict__ fc1w, const float* __restrict__ fc1b,
       const float* __restrict__ fc2w, const float* __restrict__ fc2b,
       float* __restrict__ out) {
    __shared__ float hs[8 * 256];
    __shared__ float z[8 * 128];
    const int t0 = blockIdx.x * 8;
    const int j  = threadIdx.x;

    for (int idx = j; idx < 8 * 256; idx += 128)
        hs[idx] = h1[(size_t)t0 * 256 + idx];
    __syncthreads();

    float acc[8];
    const float b = fc1b[j];
#pragma unroll
    for (int tt = 0; tt < 8; tt++) acc[tt] = b;

    const float4* wrow = (const float4*)(fc1w + (size_t)j * 256);
    for (int k4 = 0; k4 < 64; k4++) {
        float4 w4 = wrow[k4];
#pragma unroll
        for (int tt = 0; tt < 8; tt++) {
            float4 hv = *(const float4*)(hs + tt * 256 + k4 * 4);
            acc[tt] += w4.x * hv.x + w4.y * hv.y + w4.z * hv.z + w4.w * hv.w;
        }
    }
#pragma unroll
    for (int tt = 0; tt < 8; tt++) {
        float a = acc[tt];
        z[tt * 128 + j] = a > 0.f ? a : 0.01f * a;
    }
    __syncthreads();

    const int wid  = j >> 5;
    const int lane = j & 31;
#pragma unroll
    for (int q = 0; q < 2; q++) {
        int tt = wid * 2 + q;
        const float* zz = z + tt * 128;
        float s = fc2w[lane]      * zz[lane]
                + fc2w[lane + 32] * zz[lane + 32]
                + fc2w[lane + 64] * zz[lane + 64]
                + fc2w[lane + 96] * zz[lane + 96];
#pragma unroll
        for (int off = 16; off > 0; off >>= 1)
            s += __shfl_down_sync(0xFFFFFFFFu, s, off);
        if (lane == 0)
            out[t0 + tt] = s + fc2b[0];
    }
}

// ---------------- launcher ---------------------------------------------------
extern "C" void kernel_launch(void* const* d_in, const int* in_sizes, int n_in,
                              void* d_out, int out_size) {
    const float* x        = (const float*)d_in[0];
    const float* w_ih_l0  = (const float*)d_in[1];
    const float* w_hh_l0  = (const float*)d_in[2];
    const float* b_ih_l0  = (const float*)d_in[3];
    const float* b_hh_l0  = (const float*)d_in[4];
    const float* w_ih_l0r = (const float*)d_in[5];
    const float* w_hh_l0r = (const float*)d_in[6];
    const float* b_ih_l0r = (const float*)d_in[7];
    const float* b_hh_l0r = (const float*)d_in[8];
    const float* w_ih_l1  = (const float*)d_in[9];
    const float* w_hh_l1  = (const float*)d_in[10];
    const float* b_ih_l1  = (const float*)d_in[11];
    const float* b_hh_l1  = (const float*)d_in[12];
    const float* w_ih_l1r = (const float*)d_in[13];
    const float* w_hh_l1r = (const float*)d_in[14];
    const float* b_ih_l1r = (const float*)d_in[15];
    const float* b_hh_l1r = (const float*)d_in[16];
    const float* fc1_w    = (const float*)d_in[17];
    const float* fc1_b    = (const float*)d_in[18];
    const float* fc2_w    = (const float*)d_in[19];
    const float* fc2_b    = (const float*)d_in[20];
    float* out = (float*)d_out;

    float *gx_base, *h0, *h1;
    cudaGetSymbolAddress((void**)&gx_base, g_gx);
    cudaGetSymbolAddress((void**)&h0, g_h0);
    cudaGetSymbolAddress((void**)&h1, g_h1);
    float* gx0f = gx_base;
    float* gx0b = gx_base + (size_t)1 * T_LEN * G4;
    float* gx1f = gx_base + (size_t)2 * T_LEN * G4;
    float* gx1b = gx_base + (size_t)3 * T_LEN * G4;

    k_gx0<<<(T_LEN * G4 + 255) / 256, 256>>>(x, w_ih_l0, b_ih_l0, b_hh_l0,
                                             w_ih_l0r, b_ih_l0r, b_hh_l0r,
                                             gx0f, gx0b);
    k_lstm2<<<4, 512>>>(gx0f, gx0b, w_hh_l0, w_hh_l0r, h0);
    k_gx1<<<dim3(T_LEN / 32, 2), 512>>>(h0, w_ih_l1, b_ih_l1, b_hh_l1,
                                        w_ih_l1r, b_ih_l1r, b_hh_l1r,
                                        gx1f, gx1b);
    k_lstm2<<<4, 512>>>(gx1f, gx1b, w_hh_l1, w_hh_l1r, h1);
    k_head<<<T_LEN / 8, 128>>>(h1, fc1_w, fc1_b, fc2_w, fc2_b, out);
}